// round 11
// baseline (speedup 1.0000x reference)
#include <cuda_runtime.h>

#define BB   32
#define NN   1024
#define DDIM 256
#define NCAP 32
#define DCAP 64

typedef unsigned long long u64;

__device__ __forceinline__ void fma2(u64& d, u64 a, u64 b){
    asm("fma.rn.f32x2 %0, %1, %2, %0;" : "+l"(d) : "l"(a), "l"(b));
}
__device__ __forceinline__ float2 unpk(u64 v){
    float2 r; asm("mov.b64 {%0,%1}, %2;" : "=f"(r.x), "=f"(r.y) : "l"(v)); return r;
}
__device__ __forceinline__ float sum2(u64 v){ float2 r = unpk(v); return r.x + r.y; }

#define NJC 8   // j-chunks for k_x partials

// ---- scratch ----
__device__ __align__(16) float g_xpart[BB*8*DDIM];       // mean partials
__device__ __align__(16) float g_b[BB*NCAP*NN];          // routing logits
__device__ __align__(16) float g_sum[BB*NCAP];           // softmax sum-exp (no-max)
__device__ __align__(16) float g_xp[NJC*BB*NCAP*DDIM];   // x partials (8 j-chunks)
__device__ __align__(16) float g_wv[BB*NCAP*DDIM];       // W_i @ v

// ---------------------------------------------------------------------------
// K1: partial mean of u over j. grid (32 b, 8 p), 256 threads.
// ---------------------------------------------------------------------------
__global__ void k_meanpart(const float* __restrict__ u){
    int b = blockIdx.x, p = blockIdx.y, d = threadIdx.x;
    const float* up = u + ((size_t)b*NN + p*128)*DDIM + d;
    float acc = 0.f;
    #pragma unroll 8
    for (int j = 0; j < 128; ++j) acc += up[(size_t)j*DDIM];
    g_xpart[(b*8+p)*DDIM + d] = acc;
}

// ---------------------------------------------------------------------------
// K2: per (i, 8-batch group): s = x@W_i ; v = squash(s) ; w_v = W_i@v.
// grid (32 i, 4 bq), 256 threads. (unchanged from round 8)
// ---------------------------------------------------------------------------
template<int MODE>
__global__ void k_sv(const float* __restrict__ W, float* __restrict__ out){
    int i = blockIdx.x, bq = blockIdx.y;
    int t = threadIdx.x;
    extern __shared__ float Wt_s[];          // [256][66] floats (67.6 KB)
    __shared__ float2 xsD[8][DDIM];
    __shared__ float  sm[8][DCAP];
    __shared__ float  vs[8][DCAP];

    if (MODE != 2 && t < 8) g_sum[(bq*8+t)*NCAP + i] = 0.f;

    #pragma unroll 4
    for (int p = 0; p < 16; ++p){
        int idx = t + 256*p;
        int d = idx >> 4, m4 = idx & 15;
        float4 w4 = *(const float4*)(W + (size_t)d*2048 + i*64 + m4*4);
        float* wp = &Wt_s[d*66 + m4*4];
        wp[0]=w4.x; wp[1]=w4.y; wp[2]=w4.z; wp[3]=w4.w;
    }
    #pragma unroll
    for (int p = 0; p < 8; ++p){
        int idx = t + 256*p;
        int bb = idx >> 8, d = idx & 255;
        float a;
        if (MODE == 0){
            a = 0.f;
            #pragma unroll
            for (int q = 0; q < 8; ++q) a += g_xpart[(((bq*8+bb)*8)+q)*DDIM + d];
            a *= (1.0f/1024.0f);
        } else {
            size_t bi = (((size_t)(bq*8+bb))*NCAP + i)*DDIM + d;
            a = 0.f;
            #pragma unroll
            for (int q = 0; q < NJC; ++q) a += g_xp[(size_t)q*BB*NCAP*DDIM + bi];
        }
        xsD[bb][d] = make_float2(a, a);
    }
    __syncthreads();

    {
        int mp = t & 31, bb = t >> 5;
        u64 acc = 0ull;
        const u64* xrow = (const u64*)&xsD[bb][0];
        #pragma unroll 8
        for (int d = 0; d < DDIM; ++d){
            u64 w2 = *(const u64*)&Wt_s[d*66 + 2*mp];
            fma2(acc, w2, xrow[d]);
        }
        float2 sp = unpk(acc);
        sm[bb][2*mp] = sp.x; sm[bb][2*mp+1] = sp.y;
    }
    __syncthreads();

    {
        int w = t >> 5, lane = t & 31;
        float s0 = sm[w][lane], s1 = sm[w][lane+32];
        float q = s0*s0 + s1*s1;
        #pragma unroll
        for (int o = 16; o; o >>= 1) q += __shfl_xor_sync(0xffffffffu, q, o);
        float r = rsqrtf(q + 1e-7f);
        if (MODE == 2){
            size_t ob = ((size_t)(bq*8+w)*NCAP + i)*DCAP;
            out[ob + lane]      = s0*r;
            out[ob + lane + 32] = s1*r;
            return;
        }
        vs[w][lane] = s0*r; vs[w][lane+32] = s1*r;
    }
    __syncthreads();

    {
        float wv[8] = {0,0,0,0,0,0,0,0};
        #pragma unroll 8
        for (int m = 0; m < DCAP; ++m){
            float wtv = Wt_s[t*66 + m];
            #pragma unroll
            for (int b8 = 0; b8 < 8; ++b8) wv[b8] = fmaf(wtv, vs[b8][m], wv[b8]);
        }
        #pragma unroll
        for (int b8 = 0; b8 < 8; ++b8)
            g_wv[(((size_t)(bq*8+b8))*NCAP + i)*DDIM + t] = wv[b8];
    }
}

// ---------------------------------------------------------------------------
// K3: b[b,i,j] (+)= sum_d u[b,j,d]*wv[b,i,d]; epilogue: atomic sum of exp(b).
// grid (32 b, 4 jc), **512 threads (16 warps)**. Same 256j x 32i block tile
// and j-paired f32x2 inner loop as round 2/8; thread tile 8j x 2i.
// ti = t&15 -> i in {ti, ti+16}; tj = t>>4 (0..31) -> j = tj*8 .. +7.
// ---------------------------------------------------------------------------
template<bool ACC>
__global__ void __launch_bounds__(512) k_bupd(const float* __restrict__ u){
    int b = blockIdx.x, jb = blockIdx.y*256;
    int t = threadIdx.x;
    extern __shared__ float2 wvD_s[];        // [256][33] float2 (67.6 KB)
    __shared__ float As[16][256];
    __shared__ float red[16][32];

    // stage wv duplicated: wvD[d][i] = {w,w}  (8192 elems, 512 thr)
    #pragma unroll 4
    for (int p = 0; p < 16; ++p){
        int idx = t + 512*p;
        int i = idx >> 8, d = idx & 255;
        float w = g_wv[((size_t)b*NCAP + i)*DDIM + d];
        wvD_s[d*33 + i] = make_float2(w, w);
    }

    int ti = t & 15, tj = t >> 4;            // 2 i, 8 j per thread
    u64 acc[4][2];
    #pragma unroll
    for (int q = 0; q < 4; ++q){ acc[q][0] = 0ull; acc[q][1] = 0ull; }

    // staging roles: j = t & 255, dh = t >> 8 (0/1): 8 d each
    int js = t & 255, dh = t >> 8;
    const float* ub = u + ((size_t)b*NN + jb + js)*DDIM + dh*8;
    for (int dt = 0; dt < DDIM; dt += 16){
        __syncthreads();
        float4 v0 = *(const float4*)(ub + dt);
        float4 v1 = *(const float4*)(ub + dt + 4);
        As[dh*8+0][js]=v0.x; As[dh*8+1][js]=v0.y; As[dh*8+2][js]=v0.z; As[dh*8+3][js]=v0.w;
        As[dh*8+4][js]=v1.x; As[dh*8+5][js]=v1.y; As[dh*8+6][js]=v1.z; As[dh*8+7][js]=v1.w;
        __syncthreads();
        #pragma unroll
        for (int dd = 0; dd < 16; ++dd){
            u64 a0 = *(const u64*)&As[dd][tj*8 + 0];
            u64 a1 = *(const u64*)&As[dd][tj*8 + 2];
            u64 a2 = *(const u64*)&As[dd][tj*8 + 4];
            u64 a3 = *(const u64*)&As[dd][tj*8 + 6];
            const float2* wr = &wvD_s[(dt+dd)*33];
            u64 w0 = *(const u64*)&wr[ti];
            u64 w1 = *(const u64*)&wr[ti+16];
            fma2(acc[0][0], a0, w0); fma2(acc[1][0], a1, w0);
            fma2(acc[2][0], a2, w0); fma2(acc[3][0], a3, w0);
            fma2(acc[0][1], a0, w1); fma2(acc[1][1], a1, w1);
            fma2(acc[2][1], a2, w1); fma2(acc[3][1], a3, w1);
        }
    }

    // epilogue: store b (+= if ACC), accumulate exp sums per i
    float es[2];
    #pragma unroll
    for (int k = 0; k < 2; ++k){
        int i = ti + 16*k;
        float2 p0 = unpk(acc[0][k]), p1 = unpk(acc[1][k]);
        float2 p2 = unpk(acc[2][k]), p3 = unpk(acc[3][k]);
        float4 q0 = make_float4(p0.x, p0.y, p1.x, p1.y);
        float4 q1 = make_float4(p2.x, p2.y, p3.x, p3.y);
        float4* bp = (float4*)(g_b + ((size_t)b*NCAP + i)*NN + jb + tj*8);
        if (ACC){
            float4 o0 = bp[0], o1 = bp[1];
            q0.x+=o0.x; q0.y+=o0.y; q0.z+=o0.z; q0.w+=o0.w;
            q1.x+=o1.x; q1.y+=o1.y; q1.z+=o1.z; q1.w+=o1.w;
        }
        bp[0] = q0; bp[1] = q1;
        es[k] = __expf(q0.x)+__expf(q0.y)+__expf(q0.z)+__expf(q0.w)
              + __expf(q1.x)+__expf(q1.y)+__expf(q1.z)+__expf(q1.w);
    }
    // lanes l and l+16 share ti: one shfl folds the two tj's in-warp
    es[0] += __shfl_down_sync(0xffffffffu, es[0], 16);
    es[1] += __shfl_down_sync(0xffffffffu, es[1], 16);
    int w = t >> 5, lane = t & 31;
    if (lane < 16){
        red[w][lane]      = es[0];
        red[w][lane + 16] = es[1];
    }
    __syncthreads();
    if (t < 32){
        float s = 0.f;
        #pragma unroll
        for (int ww = 0; ww < 16; ++ww) s += red[ww][t];
        atomicAdd(&g_sum[b*NCAP + t], s);     // i == t
    }
}

// ---------------------------------------------------------------------------
// K4: x partial: g_xp[jc][b,i,dslice] = sum_{j in chunk} c_ij * u[j,d].
// grid (32 b, 2 dh, 8 jc), 128 thr. (unchanged — measured 33-35 us)
// ---------------------------------------------------------------------------
__global__ void k_x(const float* __restrict__ u){
    int b = blockIdx.x, dh = blockIdx.y, jc = blockIdx.z;
    int t = threadIdx.x;
    int ig = t & 7, dg = t >> 3;
    __shared__ float  Us[32][132];
    __shared__ float2 CsD[32][34];
    __shared__ float  inv[NCAP];
    if (t < 32) inv[t] = 1.0f / g_sum[b*NCAP + t];

    u64 acc[4][4];
    #pragma unroll
    for (int p = 0; p < 4; ++p)
        #pragma unroll
        for (int q = 0; q < 4; ++q) acc[p][q] = 0ull;

    int j0 = jc*128;
    for (int jt = 0; jt < 128; jt += 32){
        __syncthreads();
        #pragma unroll
        for (int p = 0; p < 8; ++p){
            int lin = t + 128*p;
            int j = lin >> 5, f4 = lin & 31;
            float4 v4 = *(const float4*)(u + ((size_t)b*NN + j0 + jt + j)*DDIM + dh*128 + f4*4);
            *(float4*)&Us[j][f4*4] = v4;
        }
        #pragma unroll
        for (int p = 0; p < 8; ++p){
            int lin = t + 128*p;
            int i = lin >> 5, jj = lin & 31;
            float bv = g_b[((size_t)b*NCAP + i)*NN + j0 + jt + jj];
            float c = __expf(bv) * inv[i];
            CsD[jj][i] = make_float2(c, c);
        }
        __syncthreads();
        #pragma unroll
        for (int jj = 0; jj < 32; ++jj){
            ulonglong2 A0 = *(const ulonglong2*)&Us[jj][dg*8];
            ulonglong2 A1 = *(const ulonglong2*)&Us[jj][dg*8 + 4];
            ulonglong2 C0 = *(const ulonglong2*)&CsD[jj][ig*4];
            ulonglong2 C1 = *(const ulonglong2*)&CsD[jj][ig*4 + 2];
            u64 a[4] = {A0.x, A0.y, A1.x, A1.y};
            u64 c[4] = {C0.x, C0.y, C1.x, C1.y};
            #pragma unroll
            for (int p = 0; p < 4; ++p)
                #pragma unroll
                for (int q = 0; q < 4; ++q)
                    fma2(acc[p][q], a[p], c[q]);
        }
    }
    #pragma unroll
    for (int q = 0; q < 4; ++q){
        int i = ig*4 + q;
        float2 r0 = unpk(acc[0][q]), r1 = unpk(acc[1][q]);
        float2 r2 = unpk(acc[2][q]), r3 = unpk(acc[3][q]);
        float* xp = g_xp + (size_t)jc*BB*NCAP*DDIM
                  + ((size_t)b*NCAP + i)*DDIM + dh*128 + dg*8;
        *(float4*)xp       = make_float4(r0.x, r0.y, r1.x, r1.y);
        *(float4*)(xp + 4) = make_float4(r2.x, r2.y, r3.x, r3.y);
    }
}

// ---------------------------------------------------------------------------
extern "C" void kernel_launch(void* const* d_in, const int* in_sizes, int n_in,
                              void* d_out, int out_size){
    const float* u = (const float*)d_in[0];
    const float* W = (const float*)d_in[1];
    if (n_in >= 2 && in_sizes[0] < in_sizes[1]){
        u = (const float*)d_in[1];
        W = (const float*)d_in[0];
    }
    float* out = (float*)d_out;

    const int SV_SMEM  = 256*66*sizeof(float);    // 67584
    const int BUP_SMEM = 256*33*sizeof(float2);   // 67584
    static bool attr_done = false;
    if (!attr_done){
        cudaFuncSetAttribute(k_sv<0>,       cudaFuncAttributeMaxDynamicSharedMemorySize, SV_SMEM);
        cudaFuncSetAttribute(k_sv<1>,       cudaFuncAttributeMaxDynamicSharedMemorySize, SV_SMEM);
        cudaFuncSetAttribute(k_sv<2>,       cudaFuncAttributeMaxDynamicSharedMemorySize, SV_SMEM);
        cudaFuncSetAttribute(k_bupd<false>, cudaFuncAttributeMaxDynamicSharedMemorySize, BUP_SMEM);
        cudaFuncSetAttribute(k_bupd<true>,  cudaFuncAttributeMaxDynamicSharedMemorySize, BUP_SMEM);
        attr_done = true;
    }

    // iter 0 (softmax of zeros == mean)
    k_meanpart   <<<dim3(32,8),   256>>>(u);
    k_sv<0>      <<<dim3(32,4),   256, SV_SMEM>>>(W, out);
    k_bupd<false><<<dim3(32,4),   512, BUP_SMEM>>>(u);
    // iter 1
    k_x          <<<dim3(32,2,8), 128>>>(u);
    k_sv<1>      <<<dim3(32,4),   256, SV_SMEM>>>(W, out);
    k_bupd<true> <<<dim3(32,4),   512, BUP_SMEM>>>(u);
    // iter 2 (final)
    k_x          <<<dim3(32,2,8), 128>>>(u);
    k_sv<2>      <<<dim3(32,4),   256, SV_SMEM>>>(W, out);
}

// round 13
// speedup vs baseline: 1.0739x; 1.0739x over previous
#include <cuda_runtime.h>

#define BB   32
#define NN   1024
#define DDIM 256
#define NCAP 32
#define DCAP 64

typedef unsigned long long u64;

__device__ __forceinline__ void fma2(u64& d, u64 a, u64 b){
    asm("fma.rn.f32x2 %0, %1, %2, %0;" : "+l"(d) : "l"(a), "l"(b));
}
__device__ __forceinline__ float2 unpk(u64 v){
    float2 r; asm("mov.b64 {%0,%1}, %2;" : "=f"(r.x), "=f"(r.y) : "l"(v)); return r;
}
__device__ __forceinline__ float sum2(u64 v){ float2 r = unpk(v); return r.x + r.y; }

#define NJC 8   // j-chunks for k_x partials

// ---- scratch ----
__device__ __align__(16) float g_xpart[BB*8*DDIM];       // mean partials
__device__ __align__(16) float g_b[BB*NCAP*NN];          // routing logits
__device__ __align__(16) float g_sum[BB*NCAP];           // softmax sum-exp (no-max)
__device__ __align__(16) float g_xp[NJC*BB*NCAP*DDIM];   // x partials (8 j-chunks)
__device__ __align__(16) float g_wv[BB*NCAP*DDIM];       // W_i @ v

// ---------------------------------------------------------------------------
// K1: partial mean of u over j. grid (32 b, 8 p), 256 threads.
// ---------------------------------------------------------------------------
__global__ void k_meanpart(const float* __restrict__ u){
    int b = blockIdx.x, p = blockIdx.y, d = threadIdx.x;
    const float* up = u + ((size_t)b*NN + p*128)*DDIM + d;
    float acc = 0.f;
    #pragma unroll 8
    for (int j = 0; j < 128; ++j) acc += up[(size_t)j*DDIM];
    g_xpart[(b*8+p)*DDIM + d] = acc;
}

// ---------------------------------------------------------------------------
// K2: per (i, 8-batch group): s = x@W_i ; v = squash(s) ; w_v = W_i@v.
// grid (32 i, 4 bq), 256 threads. (unchanged from round 8)
// ---------------------------------------------------------------------------
template<int MODE>
__global__ void k_sv(const float* __restrict__ W, float* __restrict__ out){
    int i = blockIdx.x, bq = blockIdx.y;
    int t = threadIdx.x;
    extern __shared__ float Wt_s[];          // [256][66] floats (67.6 KB)
    __shared__ float2 xsD[8][DDIM];
    __shared__ float  sm[8][DCAP];
    __shared__ float  vs[8][DCAP];

    if (MODE != 2 && t < 8) g_sum[(bq*8+t)*NCAP + i] = 0.f;

    #pragma unroll 4
    for (int p = 0; p < 16; ++p){
        int idx = t + 256*p;
        int d = idx >> 4, m4 = idx & 15;
        float4 w4 = *(const float4*)(W + (size_t)d*2048 + i*64 + m4*4);
        float* wp = &Wt_s[d*66 + m4*4];
        wp[0]=w4.x; wp[1]=w4.y; wp[2]=w4.z; wp[3]=w4.w;
    }
    #pragma unroll
    for (int p = 0; p < 8; ++p){
        int idx = t + 256*p;
        int bb = idx >> 8, d = idx & 255;
        float a;
        if (MODE == 0){
            a = 0.f;
            #pragma unroll
            for (int q = 0; q < 8; ++q) a += g_xpart[(((bq*8+bb)*8)+q)*DDIM + d];
            a *= (1.0f/1024.0f);
        } else {
            size_t bi = (((size_t)(bq*8+bb))*NCAP + i)*DDIM + d;
            a = 0.f;
            #pragma unroll
            for (int q = 0; q < NJC; ++q) a += g_xp[(size_t)q*BB*NCAP*DDIM + bi];
        }
        xsD[bb][d] = make_float2(a, a);
    }
    __syncthreads();

    {
        int mp = t & 31, bb = t >> 5;
        u64 acc = 0ull;
        const u64* xrow = (const u64*)&xsD[bb][0];
        #pragma unroll 8
        for (int d = 0; d < DDIM; ++d){
            u64 w2 = *(const u64*)&Wt_s[d*66 + 2*mp];
            fma2(acc, w2, xrow[d]);
        }
        float2 sp = unpk(acc);
        sm[bb][2*mp] = sp.x; sm[bb][2*mp+1] = sp.y;
    }
    __syncthreads();

    {
        int w = t >> 5, lane = t & 31;
        float s0 = sm[w][lane], s1 = sm[w][lane+32];
        float q = s0*s0 + s1*s1;
        #pragma unroll
        for (int o = 16; o; o >>= 1) q += __shfl_xor_sync(0xffffffffu, q, o);
        float r = rsqrtf(q + 1e-7f);
        if (MODE == 2){
            size_t ob = ((size_t)(bq*8+w)*NCAP + i)*DCAP;
            out[ob + lane]      = s0*r;
            out[ob + lane + 32] = s1*r;
            return;
        }
        vs[w][lane] = s0*r; vs[w][lane+32] = s1*r;
    }
    __syncthreads();

    {
        float wv[8] = {0,0,0,0,0,0,0,0};
        #pragma unroll 8
        for (int m = 0; m < DCAP; ++m){
            float wtv = Wt_s[t*66 + m];
            #pragma unroll
            for (int b8 = 0; b8 < 8; ++b8) wv[b8] = fmaf(wtv, vs[b8][m], wv[b8]);
        }
        #pragma unroll
        for (int b8 = 0; b8 < 8; ++b8)
            g_wv[(((size_t)(bq*8+b8))*NCAP + i)*DDIM + t] = wv[b8];
    }
}

// ---------------------------------------------------------------------------
// K3: b[b,i,j] (+)= sum_d u[b,j,d]*wv[b,i,d]; epilogue: atomic sum of exp(b).
// grid (32 b, 4 jc), 256 threads. Round-8 structure + SOFTWARE PIPELINE:
// LDGs for d-tile n+1 issue right after the stores of tile n, overlapping
// the 16-dd compute (~exposed L2 latency fully hidden).
// ---------------------------------------------------------------------------
template<bool ACC>
__global__ void __launch_bounds__(256) k_bupd(const float* __restrict__ u){
    int b = blockIdx.x, jb = blockIdx.y*256;
    int t = threadIdx.x;
    extern __shared__ float2 wvD_s[];        // [256][33] float2 (67.6 KB)
    __shared__ float As[16][256];
    __shared__ float red[8][32];

    // stage wv duplicated: wvD[d][i] = {w,w}
    #pragma unroll 8
    for (int p = 0; p < 32; ++p){
        int idx = t + 256*p;                 // 8192
        int i = idx >> 8, d = idx & 255;
        float w = g_wv[((size_t)b*NCAP + i)*DDIM + d];
        wvD_s[d*33 + i] = make_float2(w, w);
    }

    int ti = t & 7, tj = t >> 3;
    u64 acc[4][4];
    #pragma unroll
    for (int q = 0; q < 4; ++q)
        #pragma unroll
        for (int k = 0; k < 4; ++k) acc[q][k] = 0ull;

    const float* ub = u + ((size_t)b*NN + jb + t)*DDIM;
    // prologue prefetch (dt = 0)
    float4 v0 = *(const float4*)(ub +  0);
    float4 v1 = *(const float4*)(ub +  4);
    float4 v2 = *(const float4*)(ub +  8);
    float4 v3 = *(const float4*)(ub + 12);

    for (int dt = 0; dt < DDIM; dt += 16){
        __syncthreads();                      // prior tile consumed (also wvD on iter 0)
        As[ 0][t]=v0.x; As[ 1][t]=v0.y; As[ 2][t]=v0.z; As[ 3][t]=v0.w;
        As[ 4][t]=v1.x; As[ 5][t]=v1.y; As[ 6][t]=v1.z; As[ 7][t]=v1.w;
        As[ 8][t]=v2.x; As[ 9][t]=v2.y; As[10][t]=v2.z; As[11][t]=v2.w;
        As[12][t]=v3.x; As[13][t]=v3.y; As[14][t]=v3.z; As[15][t]=v3.w;
        __syncthreads();
        if (dt + 16 < DDIM){                  // prefetch next tile (overlaps compute)
            v0 = *(const float4*)(ub + dt + 16);
            v1 = *(const float4*)(ub + dt + 20);
            v2 = *(const float4*)(ub + dt + 24);
            v3 = *(const float4*)(ub + dt + 28);
        }
        #pragma unroll
        for (int dd = 0; dd < 16; ++dd){
            u64 a0 = *(const u64*)&As[dd][tj*8 + 0];
            u64 a1 = *(const u64*)&As[dd][tj*8 + 2];
            u64 a2 = *(const u64*)&As[dd][tj*8 + 4];
            u64 a3 = *(const u64*)&As[dd][tj*8 + 6];
            const float2* wr = &wvD_s[(dt+dd)*33];
            u64 w0 = *(const u64*)&wr[ti];
            u64 w1 = *(const u64*)&wr[ti+8];
            u64 w2 = *(const u64*)&wr[ti+16];
            u64 w3 = *(const u64*)&wr[ti+24];
            fma2(acc[0][0], a0, w0); fma2(acc[1][0], a1, w0);
            fma2(acc[2][0], a2, w0); fma2(acc[3][0], a3, w0);
            fma2(acc[0][1], a0, w1); fma2(acc[1][1], a1, w1);
            fma2(acc[2][1], a2, w1); fma2(acc[3][1], a3, w1);
            fma2(acc[0][2], a0, w2); fma2(acc[1][2], a1, w2);
            fma2(acc[2][2], a2, w2); fma2(acc[3][2], a3, w2);
            fma2(acc[0][3], a0, w3); fma2(acc[1][3], a1, w3);
            fma2(acc[2][3], a2, w3); fma2(acc[3][3], a3, w3);
        }
    }

    // epilogue: store b (+= if ACC), accumulate exp sums per i
    float es[4];
    #pragma unroll
    for (int k = 0; k < 4; ++k){
        int i = ti + 8*k;
        float2 p0 = unpk(acc[0][k]), p1 = unpk(acc[1][k]);
        float2 p2 = unpk(acc[2][k]), p3 = unpk(acc[3][k]);
        float4 q0 = make_float4(p0.x, p0.y, p1.x, p1.y);
        float4 q1 = make_float4(p2.x, p2.y, p3.x, p3.y);
        float4* bp = (float4*)(g_b + ((size_t)b*NCAP + i)*NN + jb + tj*8);
        if (ACC){
            float4 o0 = bp[0], o1 = bp[1];
            q0.x+=o0.x; q0.y+=o0.y; q0.z+=o0.z; q0.w+=o0.w;
            q1.x+=o1.x; q1.y+=o1.y; q1.z+=o1.z; q1.w+=o1.w;
        }
        bp[0] = q0; bp[1] = q1;
        es[k] = __expf(q0.x)+__expf(q0.y)+__expf(q0.z)+__expf(q0.w)
              + __expf(q1.x)+__expf(q1.y)+__expf(q1.z)+__expf(q1.w);
    }
    #pragma unroll
    for (int k = 0; k < 4; ++k){
        es[k] += __shfl_down_sync(0xffffffffu, es[k], 16);
        es[k] += __shfl_down_sync(0xffffffffu, es[k], 8);
    }
    int w = t >> 5, lane = t & 31;
    if (lane < 8){
        #pragma unroll
        for (int k = 0; k < 4; ++k) red[w][k*8 + lane] = es[k];
    }
    __syncthreads();
    if (t < 32){
        float s = 0.f;
        #pragma unroll
        for (int ww = 0; ww < 8; ++ww) s += red[ww][t];
        atomicAdd(&g_sum[b*NCAP + t], s);     // i == t
    }
}

// ---------------------------------------------------------------------------
// K4: x partial: g_xp[jc][b,i,dslice] = sum_{j in chunk} c_ij * u[j,d].
// grid (32 b, 2 dh, 8 jc), 128 thr. Round-3/8 structure + SOFTWARE PIPELINE:
// next tile's u rows and b logits prefetched into regs during compute.
// ---------------------------------------------------------------------------
__global__ void __launch_bounds__(128) k_x(const float* __restrict__ u){
    int b = blockIdx.x, dh = blockIdx.y, jc = blockIdx.z;
    int t = threadIdx.x;
    int ig = t & 7, dg = t >> 3;
    __shared__ float  Us[32][132];
    __shared__ float2 CsD[32][34];
    __shared__ float  inv[NCAP];
    if (t < 32) inv[t] = 1.0f / g_sum[b*NCAP + t];

    u64 acc[4][4];
    #pragma unroll
    for (int p = 0; p < 4; ++p)
        #pragma unroll
        for (int q = 0; q < 4; ++q) acc[p][q] = 0ull;

    int j0 = jc*128;
    // staging roles (fixed per thread)
    int sj = t >> 5;            // Us: base j (lin>>5 for p strides of 128 -> j = sj + 4p... )
    int sf = t & 31;            // Us: float4 column
    int sci = t >> 5;           //  c: base i
    int scj = t & 31;           //  c: j within tile

    // prologue prefetch (jt = 0)
    float4 pU[8]; float pB[8];
    #pragma unroll
    for (int p = 0; p < 8; ++p){
        int j = sj + 4*p;       // (t+128p)>>5 = sj + 4p
        pU[p] = *(const float4*)(u + ((size_t)b*NN + j0 + j)*DDIM + dh*128 + sf*4);
        int i = sci + 4*p;
        pB[p] = g_b[((size_t)b*NCAP + i)*NN + j0 + scj];
    }

    for (int jt = 0; jt < 128; jt += 32){
        __syncthreads();
        // store phase
        #pragma unroll
        for (int p = 0; p < 8; ++p){
            int j = sj + 4*p;
            *(float4*)&Us[j][sf*4] = pU[p];
            int i = sci + 4*p;
            float c = __expf(pB[p]) * inv[i];
            CsD[scj][i] = make_float2(c, c);
        }
        __syncthreads();
        if (jt + 32 < 128){     // prefetch next tile (overlaps compute)
            #pragma unroll
            for (int p = 0; p < 8; ++p){
                int j = sj + 4*p;
                pU[p] = *(const float4*)(u + ((size_t)b*NN + j0 + jt + 32 + j)*DDIM + dh*128 + sf*4);
                int i = sci + 4*p;
                pB[p] = g_b[((size_t)b*NCAP + i)*NN + j0 + jt + 32 + scj];
            }
        }
        #pragma unroll
        for (int jj = 0; jj < 32; ++jj){
            ulonglong2 A0 = *(const ulonglong2*)&Us[jj][dg*8];
            ulonglong2 A1 = *(const ulonglong2*)&Us[jj][dg*8 + 4];
            ulonglong2 C0 = *(const ulonglong2*)&CsD[jj][ig*4];
            ulonglong2 C1 = *(const ulonglong2*)&CsD[jj][ig*4 + 2];
            u64 a[4] = {A0.x, A0.y, A1.x, A1.y};
            u64 c[4] = {C0.x, C0.y, C1.x, C1.y};
            #pragma unroll
            for (int p = 0; p < 4; ++p)
                #pragma unroll
                for (int q = 0; q < 4; ++q)
                    fma2(acc[p][q], a[p], c[q]);
        }
    }
    #pragma unroll
    for (int q = 0; q < 4; ++q){
        int i = ig*4 + q;
        float2 r0 = unpk(acc[0][q]), r1 = unpk(acc[1][q]);
        float2 r2 = unpk(acc[2][q]), r3 = unpk(acc[3][q]);
        float* xp = g_xp + (size_t)jc*BB*NCAP*DDIM
                  + ((size_t)b*NCAP + i)*DDIM + dh*128 + dg*8;
        *(float4*)xp       = make_float4(r0.x, r0.y, r1.x, r1.y);
        *(float4*)(xp + 4) = make_float4(r2.x, r2.y, r3.x, r3.y);
    }
}

// ---------------------------------------------------------------------------
extern "C" void kernel_launch(void* const* d_in, const int* in_sizes, int n_in,
                              void* d_out, int out_size){
    const float* u = (const float*)d_in[0];
    const float* W = (const float*)d_in[1];
    if (n_in >= 2 && in_sizes[0] < in_sizes[1]){
        u = (const float*)d_in[1];
        W = (const float*)d_in[0];
    }
    float* out = (float*)d_out;

    const int SV_SMEM  = 256*66*sizeof(float);    // 67584
    const int BUP_SMEM = 256*33*sizeof(float2);   // 67584
    static bool attr_done = false;
    if (!attr_done){
        cudaFuncSetAttribute(k_sv<0>,       cudaFuncAttributeMaxDynamicSharedMemorySize, SV_SMEM);
        cudaFuncSetAttribute(k_sv<1>,       cudaFuncAttributeMaxDynamicSharedMemorySize, SV_SMEM);
        cudaFuncSetAttribute(k_sv<2>,       cudaFuncAttributeMaxDynamicSharedMemorySize, SV_SMEM);
        cudaFuncSetAttribute(k_bupd<false>, cudaFuncAttributeMaxDynamicSharedMemorySize, BUP_SMEM);
        cudaFuncSetAttribute(k_bupd<true>,  cudaFuncAttributeMaxDynamicSharedMemorySize, BUP_SMEM);
        attr_done = true;
    }

    // iter 0 (softmax of zeros == mean)
    k_meanpart   <<<dim3(32,8),   256>>>(u);
    k_sv<0>      <<<dim3(32,4),   256, SV_SMEM>>>(W, out);
    k_bupd<false><<<dim3(32,4),   256, BUP_SMEM>>>(u);
    // iter 1
    k_x          <<<dim3(32,2,8), 128>>>(u);
    k_sv<1>      <<<dim3(32,4),   256, SV_SMEM>>>(W, out);
    k_bupd<true> <<<dim3(32,4),   256, BUP_SMEM>>>(u);
    // iter 2 (final)
    k_x          <<<dim3(32,2,8), 128>>>(u);
    k_sv<2>      <<<dim3(32,4),   256, SV_SMEM>>>(W, out);
}

// round 14
// speedup vs baseline: 1.2375x; 1.1524x over previous
#include <cuda_runtime.h>

#define BB   32
#define NN   1024
#define DDIM 256
#define NCAP 32
#define DCAP 64

typedef unsigned long long u64;

__device__ __forceinline__ void fma2(u64& d, u64 a, u64 b){
    asm("fma.rn.f32x2 %0, %1, %2, %0;" : "+l"(d) : "l"(a), "l"(b));
}
__device__ __forceinline__ float2 unpk(u64 v){
    float2 r; asm("mov.b64 {%0,%1}, %2;" : "=f"(r.x), "=f"(r.y) : "l"(v)); return r;
}
__device__ __forceinline__ float sum2(u64 v){ float2 r = unpk(v); return r.x + r.y; }
__device__ __forceinline__ u64 dupf(float f){
    u64 r; asm("mov.b64 %0, {%1,%1};" : "=l"(r) : "f"(f)); return r;
}

#define NJC 8   // j-chunks for k_x partials

// ---- scratch ----
__device__ __align__(16) float g_xpart[BB*8*DDIM];       // mean partials
__device__ __align__(16) float g_b[BB*NCAP*NN];          // routing logits
__device__ __align__(16) float g_sum[BB*NCAP];           // softmax sum-exp (no-max)
__device__ __align__(16) float g_xp[NJC*BB*NCAP*DDIM];   // x partials (8 j-chunks)
__device__ __align__(16) float g_wv[BB*NCAP*DDIM];       // W_i @ v

// ---------------------------------------------------------------------------
// K1: partial mean of u over j. grid (32 b, 8 p), 256 threads.
// ---------------------------------------------------------------------------
__global__ void k_meanpart(const float* __restrict__ u){
    int b = blockIdx.x, p = blockIdx.y, d = threadIdx.x;
    const float* up = u + ((size_t)b*NN + p*128)*DDIM + d;
    float acc = 0.f;
    #pragma unroll 8
    for (int j = 0; j < 128; ++j) acc += up[(size_t)j*DDIM];
    g_xpart[(b*8+p)*DDIM + d] = acc;
}

// ---------------------------------------------------------------------------
// K2: per (i, 8-batch group): s = x@W_i ; v = squash(s) ; w_v = W_i@v.
// grid (32 i, 4 bq), 256 threads. (unchanged)
// ---------------------------------------------------------------------------
template<int MODE>
__global__ void k_sv(const float* __restrict__ W, float* __restrict__ out){
    int i = blockIdx.x, bq = blockIdx.y;
    int t = threadIdx.x;
    extern __shared__ float Wt_s[];          // [256][66] floats (67.6 KB)
    __shared__ float2 xsD[8][DDIM];
    __shared__ float  sm[8][DCAP];
    __shared__ float  vs[8][DCAP];

    if (MODE != 2 && t < 8) g_sum[(bq*8+t)*NCAP + i] = 0.f;

    #pragma unroll 4
    for (int p = 0; p < 16; ++p){
        int idx = t + 256*p;
        int d = idx >> 4, m4 = idx & 15;
        float4 w4 = *(const float4*)(W + (size_t)d*2048 + i*64 + m4*4);
        float* wp = &Wt_s[d*66 + m4*4];
        wp[0]=w4.x; wp[1]=w4.y; wp[2]=w4.z; wp[3]=w4.w;
    }
    #pragma unroll
    for (int p = 0; p < 8; ++p){
        int idx = t + 256*p;
        int bb = idx >> 8, d = idx & 255;
        float a;
        if (MODE == 0){
            a = 0.f;
            #pragma unroll
            for (int q = 0; q < 8; ++q) a += g_xpart[(((bq*8+bb)*8)+q)*DDIM + d];
            a *= (1.0f/1024.0f);
        } else {
            size_t bi = (((size_t)(bq*8+bb))*NCAP + i)*DDIM + d;
            a = 0.f;
            #pragma unroll
            for (int q = 0; q < NJC; ++q) a += g_xp[(size_t)q*BB*NCAP*DDIM + bi];
        }
        xsD[bb][d] = make_float2(a, a);
    }
    __syncthreads();

    {
        int mp = t & 31, bb = t >> 5;
        u64 acc = 0ull;
        const u64* xrow = (const u64*)&xsD[bb][0];
        #pragma unroll 8
        for (int d = 0; d < DDIM; ++d){
            u64 w2 = *(const u64*)&Wt_s[d*66 + 2*mp];
            fma2(acc, w2, xrow[d]);
        }
        float2 sp = unpk(acc);
        sm[bb][2*mp] = sp.x; sm[bb][2*mp+1] = sp.y;
    }
    __syncthreads();

    {
        int w = t >> 5, lane = t & 31;
        float s0 = sm[w][lane], s1 = sm[w][lane+32];
        float q = s0*s0 + s1*s1;
        #pragma unroll
        for (int o = 16; o; o >>= 1) q += __shfl_xor_sync(0xffffffffu, q, o);
        float r = rsqrtf(q + 1e-7f);
        if (MODE == 2){
            size_t ob = ((size_t)(bq*8+w)*NCAP + i)*DCAP;
            out[ob + lane]      = s0*r;
            out[ob + lane + 32] = s1*r;
            return;
        }
        vs[w][lane] = s0*r; vs[w][lane+32] = s1*r;
    }
    __syncthreads();

    {
        float wv[8] = {0,0,0,0,0,0,0,0};
        #pragma unroll 8
        for (int m = 0; m < DCAP; ++m){
            float wtv = Wt_s[t*66 + m];
            #pragma unroll
            for (int b8 = 0; b8 < 8; ++b8) wv[b8] = fmaf(wtv, vs[b8][m], wv[b8]);
        }
        #pragma unroll
        for (int b8 = 0; b8 < 8; ++b8)
            g_wv[(((size_t)(bq*8+b8))*NCAP + i)*DDIM + t] = wv[b8];
    }
}

// ---------------------------------------------------------------------------
// K3: b update + exp-sum. grid (32 b, 4 jc), 256 threads, software-pipelined.
// (unchanged from round 13 — measured win)
// ---------------------------------------------------------------------------
template<bool ACC>
__global__ void __launch_bounds__(256) k_bupd(const float* __restrict__ u){
    int b = blockIdx.x, jb = blockIdx.y*256;
    int t = threadIdx.x;
    extern __shared__ float2 wvD_s[];        // [256][33] float2 (67.6 KB)
    __shared__ float As[16][256];
    __shared__ float red[8][32];

    #pragma unroll 8
    for (int p = 0; p < 32; ++p){
        int idx = t + 256*p;
        int i = idx >> 8, d = idx & 255;
        float w = g_wv[((size_t)b*NCAP + i)*DDIM + d];
        wvD_s[d*33 + i] = make_float2(w, w);
    }

    int ti = t & 7, tj = t >> 3;
    u64 acc[4][4];
    #pragma unroll
    for (int q = 0; q < 4; ++q)
        #pragma unroll
        for (int k = 0; k < 4; ++k) acc[q][k] = 0ull;

    const float* ub = u + ((size_t)b*NN + jb + t)*DDIM;
    float4 v0 = *(const float4*)(ub +  0);
    float4 v1 = *(const float4*)(ub +  4);
    float4 v2 = *(const float4*)(ub +  8);
    float4 v3 = *(const float4*)(ub + 12);

    for (int dt = 0; dt < DDIM; dt += 16){
        __syncthreads();
        As[ 0][t]=v0.x; As[ 1][t]=v0.y; As[ 2][t]=v0.z; As[ 3][t]=v0.w;
        As[ 4][t]=v1.x; As[ 5][t]=v1.y; As[ 6][t]=v1.z; As[ 7][t]=v1.w;
        As[ 8][t]=v2.x; As[ 9][t]=v2.y; As[10][t]=v2.z; As[11][t]=v2.w;
        As[12][t]=v3.x; As[13][t]=v3.y; As[14][t]=v3.z; As[15][t]=v3.w;
        __syncthreads();
        if (dt + 16 < DDIM){
            v0 = *(const float4*)(ub + dt + 16);
            v1 = *(const float4*)(ub + dt + 20);
            v2 = *(const float4*)(ub + dt + 24);
            v3 = *(const float4*)(ub + dt + 28);
        }
        #pragma unroll
        for (int dd = 0; dd < 16; ++dd){
            u64 a0 = *(const u64*)&As[dd][tj*8 + 0];
            u64 a1 = *(const u64*)&As[dd][tj*8 + 2];
            u64 a2 = *(const u64*)&As[dd][tj*8 + 4];
            u64 a3 = *(const u64*)&As[dd][tj*8 + 6];
            const float2* wr = &wvD_s[(dt+dd)*33];
            u64 w0 = *(const u64*)&wr[ti];
            u64 w1 = *(const u64*)&wr[ti+8];
            u64 w2 = *(const u64*)&wr[ti+16];
            u64 w3 = *(const u64*)&wr[ti+24];
            fma2(acc[0][0], a0, w0); fma2(acc[1][0], a1, w0);
            fma2(acc[2][0], a2, w0); fma2(acc[3][0], a3, w0);
            fma2(acc[0][1], a0, w1); fma2(acc[1][1], a1, w1);
            fma2(acc[2][1], a2, w1); fma2(acc[3][1], a3, w1);
            fma2(acc[0][2], a0, w2); fma2(acc[1][2], a1, w2);
            fma2(acc[2][2], a2, w2); fma2(acc[3][2], a3, w2);
            fma2(acc[0][3], a0, w3); fma2(acc[1][3], a1, w3);
            fma2(acc[2][3], a2, w3); fma2(acc[3][3], a3, w3);
        }
    }

    float es[4];
    #pragma unroll
    for (int k = 0; k < 4; ++k){
        int i = ti + 8*k;
        float2 p0 = unpk(acc[0][k]), p1 = unpk(acc[1][k]);
        float2 p2 = unpk(acc[2][k]), p3 = unpk(acc[3][k]);
        float4 q0 = make_float4(p0.x, p0.y, p1.x, p1.y);
        float4 q1 = make_float4(p2.x, p2.y, p3.x, p3.y);
        float4* bp = (float4*)(g_b + ((size_t)b*NCAP + i)*NN + jb + tj*8);
        if (ACC){
            float4 o0 = bp[0], o1 = bp[1];
            q0.x+=o0.x; q0.y+=o0.y; q0.z+=o0.z; q0.w+=o0.w;
            q1.x+=o1.x; q1.y+=o1.y; q1.z+=o1.z; q1.w+=o1.w;
        }
        bp[0] = q0; bp[1] = q1;
        es[k] = __expf(q0.x)+__expf(q0.y)+__expf(q0.z)+__expf(q0.w)
              + __expf(q1.x)+__expf(q1.y)+__expf(q1.z)+__expf(q1.w);
    }
    #pragma unroll
    for (int k = 0; k < 4; ++k){
        es[k] += __shfl_down_sync(0xffffffffu, es[k], 16);
        es[k] += __shfl_down_sync(0xffffffffu, es[k], 8);
    }
    int w = t >> 5, lane = t & 31;
    if (lane < 8){
        #pragma unroll
        for (int k = 0; k < 4; ++k) red[w][k*8 + lane] = es[k];
    }
    __syncthreads();
    if (t < 32){
        float s = 0.f;
        #pragma unroll
        for (int ww = 0; ww < 8; ++ww) s += red[ww][t];
        atomicAdd(&g_sum[b*NCAP + t], s);
    }
}

// ---------------------------------------------------------------------------
// K4: x partial. grid (32 b, 2 dh, 8 jc), 128 thr, pipelined.
// C operand DE-DUPLICATED: Cs stored scalar in [i][37] layout, inner loop
// does 4x LDS.32 + mov.b64 {c,c}. Crossbar bytes/warp-jj: 384 -> 256.
// ---------------------------------------------------------------------------
__global__ void __launch_bounds__(128) k_x(const float* __restrict__ u){
    int b = blockIdx.x, dh = blockIdx.y, jc = blockIdx.z;
    int t = threadIdx.x;
    int ig = t & 7, dg = t >> 3;
    __shared__ float Us[32][132];            // [j][128 d]
    __shared__ float Cs[32][37];             // [i][j] scalars, pad 37
    __shared__ float inv[NCAP];
    if (t < 32) inv[t] = 1.0f / g_sum[b*NCAP + t];

    u64 acc[4][4];
    #pragma unroll
    for (int p = 0; p < 4; ++p)
        #pragma unroll
        for (int q = 0; q < 4; ++q) acc[p][q] = 0ull;

    int j0 = jc*128;
    int sj = t >> 5;            // Us: base j
    int sf = t & 31;            // Us: float4 column
    int sci = t >> 5;           //  c: base i
    int scj = t & 31;           //  c: j within tile

    // prologue prefetch (jt = 0)
    float4 pU[8]; float pB[8];
    #pragma unroll
    for (int p = 0; p < 8; ++p){
        int j = sj + 4*p;
        pU[p] = *(const float4*)(u + ((size_t)b*NN + j0 + j)*DDIM + dh*128 + sf*4);
        int i = sci + 4*p;
        pB[p] = g_b[((size_t)b*NCAP + i)*NN + j0 + scj];
    }

    for (int jt = 0; jt < 128; jt += 32){
        __syncthreads();
        #pragma unroll
        for (int p = 0; p < 8; ++p){
            int j = sj + 4*p;
            *(float4*)&Us[j][sf*4] = pU[p];
            int i = sci + 4*p;
            Cs[i][scj] = __expf(pB[p]) * inv[i];   // scalar store, banks=scj distinct
        }
        __syncthreads();
        if (jt + 32 < 128){
            #pragma unroll
            for (int p = 0; p < 8; ++p){
                int j = sj + 4*p;
                pU[p] = *(const float4*)(u + ((size_t)b*NN + j0 + jt + 32 + j)*DDIM + dh*128 + sf*4);
                int i = sci + 4*p;
                pB[p] = g_b[((size_t)b*NCAP + i)*NN + j0 + jt + 32 + scj];
            }
        }
        #pragma unroll
        for (int jj = 0; jj < 32; ++jj){
            ulonglong2 A0 = *(const ulonglong2*)&Us[jj][dg*8];
            ulonglong2 A1 = *(const ulonglong2*)&Us[jj][dg*8 + 4];
            u64 a[4] = {A0.x, A0.y, A1.x, A1.y};
            u64 c0 = dupf(Cs[ig*4+0][jj]);
            u64 c1 = dupf(Cs[ig*4+1][jj]);
            u64 c2 = dupf(Cs[ig*4+2][jj]);
            u64 c3 = dupf(Cs[ig*4+3][jj]);
            #pragma unroll
            for (int p = 0; p < 4; ++p){
                fma2(acc[p][0], a[p], c0);
                fma2(acc[p][1], a[p], c1);
                fma2(acc[p][2], a[p], c2);
                fma2(acc[p][3], a[p], c3);
            }
        }
    }
    #pragma unroll
    for (int q = 0; q < 4; ++q){
        int i = ig*4 + q;
        float2 r0 = unpk(acc[0][q]), r1 = unpk(acc[1][q]);
        float2 r2 = unpk(acc[2][q]), r3 = unpk(acc[3][q]);
        float* xp = g_xp + (size_t)jc*BB*NCAP*DDIM
                  + ((size_t)b*NCAP + i)*DDIM + dh*128 + dg*8;
        *(float4*)xp       = make_float4(r0.x, r0.y, r1.x, r1.y);
        *(float4*)(xp + 4) = make_float4(r2.x, r2.y, r3.x, r3.y);
    }
}

// ---------------------------------------------------------------------------
extern "C" void kernel_launch(void* const* d_in, const int* in_sizes, int n_in,
                              void* d_out, int out_size){
    const float* u = (const float*)d_in[0];
    const float* W = (const float*)d_in[1];
    if (n_in >= 2 && in_sizes[0] < in_sizes[1]){
        u = (const float*)d_in[1];
        W = (const float*)d_in[0];
    }
    float* out = (float*)d_out;

    const int SV_SMEM  = 256*66*sizeof(float);    // 67584
    const int BUP_SMEM = 256*33*sizeof(float2);   // 67584
    static bool attr_done = false;
    if (!attr_done){
        cudaFuncSetAttribute(k_sv<0>,       cudaFuncAttributeMaxDynamicSharedMemorySize, SV_SMEM);
        cudaFuncSetAttribute(k_sv<1>,       cudaFuncAttributeMaxDynamicSharedMemorySize, SV_SMEM);
        cudaFuncSetAttribute(k_sv<2>,       cudaFuncAttributeMaxDynamicSharedMemorySize, SV_SMEM);
        cudaFuncSetAttribute(k_bupd<false>, cudaFuncAttributeMaxDynamicSharedMemorySize, BUP_SMEM);
        cudaFuncSetAttribute(k_bupd<true>,  cudaFuncAttributeMaxDynamicSharedMemorySize, BUP_SMEM);
        attr_done = true;
    }

    // iter 0 (softmax of zeros == mean)
    k_meanpart   <<<dim3(32,8),   256>>>(u);
    k_sv<0>      <<<dim3(32,4),   256, SV_SMEM>>>(W, out);
    k_bupd<false><<<dim3(32,4),   256, BUP_SMEM>>>(u);
    // iter 1
    k_x          <<<dim3(32,2,8), 128>>>(u);
    k_sv<1>      <<<dim3(32,4),   256, SV_SMEM>>>(W, out);
    k_bupd<true> <<<dim3(32,4),   256, BUP_SMEM>>>(u);
    // iter 2 (final)
    k_x          <<<dim3(32,2,8), 128>>>(u);
    k_sv<2>      <<<dim3(32,4),   256, SV_SMEM>>>(W, out);
}

// round 15
// speedup vs baseline: 1.3197x; 1.0664x over previous
#include <cuda_runtime.h>

#define BB   32
#define NN   1024
#define DDIM 256
#define NCAP 32
#define DCAP 64

typedef unsigned long long u64;

__device__ __forceinline__ void fma2(u64& d, u64 a, u64 b){
    asm("fma.rn.f32x2 %0, %1, %2, %0;" : "+l"(d) : "l"(a), "l"(b));
}
__device__ __forceinline__ float2 unpk(u64 v){
    float2 r; asm("mov.b64 {%0,%1}, %2;" : "=f"(r.x), "=f"(r.y) : "l"(v)); return r;
}
__device__ __forceinline__ float sum2(u64 v){ float2 r = unpk(v); return r.x + r.y; }
__device__ __forceinline__ u64 dupf(float f){
    u64 r; asm("mov.b64 %0, {%1,%1};" : "=l"(r) : "f"(f)); return r;
}

#define NJC 8   // j-chunks for k_x partials

// ---- scratch ----
__device__ __align__(16) float g_xpart[BB*8*DDIM];       // mean partials
__device__ __align__(16) float g_b[BB*NCAP*NN];          // routing logits
__device__ __align__(16) float g_sum[BB*NCAP];           // softmax sum-exp (no-max)
__device__ __align__(16) float g_xp[NJC*BB*NCAP*DDIM];   // x partials (8 j-chunks)
__device__ __align__(16) float g_wv[BB*NCAP*DDIM];       // W_i @ v

// ---------------------------------------------------------------------------
// K1: partial mean of u over j. grid (32 b, 8 p), 256 threads.
// ---------------------------------------------------------------------------
__global__ void k_meanpart(const float* __restrict__ u){
    int b = blockIdx.x, p = blockIdx.y, d = threadIdx.x;
    const float* up = u + ((size_t)b*NN + p*128)*DDIM + d;
    float acc = 0.f;
    #pragma unroll 8
    for (int j = 0; j < 128; ++j) acc += up[(size_t)j*DDIM];
    g_xpart[(b*8+p)*DDIM + d] = acc;
}

// ---------------------------------------------------------------------------
// K2: per (i, 8-batch group): s = x@W_i ; v = squash(s) ; w_v = W_i@v.
// grid (32 i, 4 bq), 256 threads. (unchanged)
// ---------------------------------------------------------------------------
template<int MODE>
__global__ void k_sv(const float* __restrict__ W, float* __restrict__ out){
    int i = blockIdx.x, bq = blockIdx.y;
    int t = threadIdx.x;
    extern __shared__ float Wt_s[];          // [256][66] floats (67.6 KB)
    __shared__ float2 xsD[8][DDIM];
    __shared__ float  sm[8][DCAP];
    __shared__ float  vs[8][DCAP];

    if (MODE != 2 && t < 8) g_sum[(bq*8+t)*NCAP + i] = 0.f;

    #pragma unroll 4
    for (int p = 0; p < 16; ++p){
        int idx = t + 256*p;
        int d = idx >> 4, m4 = idx & 15;
        float4 w4 = *(const float4*)(W + (size_t)d*2048 + i*64 + m4*4);
        float* wp = &Wt_s[d*66 + m4*4];
        wp[0]=w4.x; wp[1]=w4.y; wp[2]=w4.z; wp[3]=w4.w;
    }
    #pragma unroll
    for (int p = 0; p < 8; ++p){
        int idx = t + 256*p;
        int bb = idx >> 8, d = idx & 255;
        float a;
        if (MODE == 0){
            a = 0.f;
            #pragma unroll
            for (int q = 0; q < 8; ++q) a += g_xpart[(((bq*8+bb)*8)+q)*DDIM + d];
            a *= (1.0f/1024.0f);
        } else {
            size_t bi = (((size_t)(bq*8+bb))*NCAP + i)*DDIM + d;
            a = 0.f;
            #pragma unroll
            for (int q = 0; q < NJC; ++q) a += g_xp[(size_t)q*BB*NCAP*DDIM + bi];
        }
        xsD[bb][d] = make_float2(a, a);
    }
    __syncthreads();

    {
        int mp = t & 31, bb = t >> 5;
        u64 acc = 0ull;
        const u64* xrow = (const u64*)&xsD[bb][0];
        #pragma unroll 8
        for (int d = 0; d < DDIM; ++d){
            u64 w2 = *(const u64*)&Wt_s[d*66 + 2*mp];
            fma2(acc, w2, xrow[d]);
        }
        float2 sp = unpk(acc);
        sm[bb][2*mp] = sp.x; sm[bb][2*mp+1] = sp.y;
    }
    __syncthreads();

    {
        int w = t >> 5, lane = t & 31;
        float s0 = sm[w][lane], s1 = sm[w][lane+32];
        float q = s0*s0 + s1*s1;
        #pragma unroll
        for (int o = 16; o; o >>= 1) q += __shfl_xor_sync(0xffffffffu, q, o);
        float r = rsqrtf(q + 1e-7f);
        if (MODE == 2){
            size_t ob = ((size_t)(bq*8+w)*NCAP + i)*DCAP;
            out[ob + lane]      = s0*r;
            out[ob + lane + 32] = s1*r;
            return;
        }
        vs[w][lane] = s0*r; vs[w][lane+32] = s1*r;
    }
    __syncthreads();

    {
        float wv[8] = {0,0,0,0,0,0,0,0};
        #pragma unroll 8
        for (int m = 0; m < DCAP; ++m){
            float wtv = Wt_s[t*66 + m];
            #pragma unroll
            for (int b8 = 0; b8 < 8; ++b8) wv[b8] = fmaf(wtv, vs[b8][m], wv[b8]);
        }
        #pragma unroll
        for (int b8 = 0; b8 < 8; ++b8)
            g_wv[(((size_t)(bq*8+b8))*NCAP + i)*DDIM + t] = wv[b8];
    }
}

// ---------------------------------------------------------------------------
// K3: b update + exp-sum. grid (32 b, 4 jc), 256 threads, software-pipelined.
// wv operand DE-DUPLICATED (round-14 k_x trick): wvS scalar [256][33],
// inner loop 4x LDS.32 + mov.b64 {w,w}. Crossbar/warp-dd: 384 -> 256 B.
// smem halves to 33.8 KB.
// ---------------------------------------------------------------------------
template<bool ACC>
__global__ void __launch_bounds__(256) k_bupd(const float* __restrict__ u){
    int b = blockIdx.x, jb = blockIdx.y*256;
    int t = threadIdx.x;
    extern __shared__ float wvS[];           // [256][33] floats (33.8 KB)
    __shared__ float As[16][256];
    __shared__ float red[8][32];

    // stage wv scalar: wvS[d*33 + i] (stride-33 rows, conflict-free)
    #pragma unroll 8
    for (int p = 0; p < 32; ++p){
        int idx = t + 256*p;                 // 8192
        int i = idx >> 8, d = idx & 255;
        wvS[d*33 + i] = g_wv[((size_t)b*NCAP + i)*DDIM + d];
    }

    int ti = t & 7, tj = t >> 3;
    u64 acc[4][4];
    #pragma unroll
    for (int q = 0; q < 4; ++q)
        #pragma unroll
        for (int k = 0; k < 4; ++k) acc[q][k] = 0ull;

    const float* ub = u + ((size_t)b*NN + jb + t)*DDIM;
    float4 v0 = *(const float4*)(ub +  0);
    float4 v1 = *(const float4*)(ub +  4);
    float4 v2 = *(const float4*)(ub +  8);
    float4 v3 = *(const float4*)(ub + 12);

    for (int dt = 0; dt < DDIM; dt += 16){
        __syncthreads();
        As[ 0][t]=v0.x; As[ 1][t]=v0.y; As[ 2][t]=v0.z; As[ 3][t]=v0.w;
        As[ 4][t]=v1.x; As[ 5][t]=v1.y; As[ 6][t]=v1.z; As[ 7][t]=v1.w;
        As[ 8][t]=v2.x; As[ 9][t]=v2.y; As[10][t]=v2.z; As[11][t]=v2.w;
        As[12][t]=v3.x; As[13][t]=v3.y; As[14][t]=v3.z; As[15][t]=v3.w;
        __syncthreads();
        if (dt + 16 < DDIM){
            v0 = *(const float4*)(ub + dt + 16);
            v1 = *(const float4*)(ub + dt + 20);
            v2 = *(const float4*)(ub + dt + 24);
            v3 = *(const float4*)(ub + dt + 28);
        }
        #pragma unroll
        for (int dd = 0; dd < 16; ++dd){
            u64 a0 = *(const u64*)&As[dd][tj*8 + 0];
            u64 a1 = *(const u64*)&As[dd][tj*8 + 2];
            u64 a2 = *(const u64*)&As[dd][tj*8 + 4];
            u64 a3 = *(const u64*)&As[dd][tj*8 + 6];
            const float* wr = &wvS[(dt+dd)*33];
            u64 w0 = dupf(wr[ti]);
            u64 w1 = dupf(wr[ti+8]);
            u64 w2 = dupf(wr[ti+16]);
            u64 w3 = dupf(wr[ti+24]);
            fma2(acc[0][0], a0, w0); fma2(acc[1][0], a1, w0);
            fma2(acc[2][0], a2, w0); fma2(acc[3][0], a3, w0);
            fma2(acc[0][1], a0, w1); fma2(acc[1][1], a1, w1);
            fma2(acc[2][1], a2, w1); fma2(acc[3][1], a3, w1);
            fma2(acc[0][2], a0, w2); fma2(acc[1][2], a1, w2);
            fma2(acc[2][2], a2, w2); fma2(acc[3][2], a3, w2);
            fma2(acc[0][3], a0, w3); fma2(acc[1][3], a1, w3);
            fma2(acc[2][3], a2, w3); fma2(acc[3][3], a3, w3);
        }
    }

    float es[4];
    #pragma unroll
    for (int k = 0; k < 4; ++k){
        int i = ti + 8*k;
        float2 p0 = unpk(acc[0][k]), p1 = unpk(acc[1][k]);
        float2 p2 = unpk(acc[2][k]), p3 = unpk(acc[3][k]);
        float4 q0 = make_float4(p0.x, p0.y, p1.x, p1.y);
        float4 q1 = make_float4(p2.x, p2.y, p3.x, p3.y);
        float4* bp = (float4*)(g_b + ((size_t)b*NCAP + i)*NN + jb + tj*8);
        if (ACC){
            float4 o0 = bp[0], o1 = bp[1];
            q0.x+=o0.x; q0.y+=o0.y; q0.z+=o0.z; q0.w+=o0.w;
            q1.x+=o1.x; q1.y+=o1.y; q1.z+=o1.z; q1.w+=o1.w;
        }
        bp[0] = q0; bp[1] = q1;
        es[k] = __expf(q0.x)+__expf(q0.y)+__expf(q0.z)+__expf(q0.w)
              + __expf(q1.x)+__expf(q1.y)+__expf(q1.z)+__expf(q1.w);
    }
    #pragma unroll
    for (int k = 0; k < 4; ++k){
        es[k] += __shfl_down_sync(0xffffffffu, es[k], 16);
        es[k] += __shfl_down_sync(0xffffffffu, es[k], 8);
    }
    int w = t >> 5, lane = t & 31;
    if (lane < 8){
        #pragma unroll
        for (int k = 0; k < 4; ++k) red[w][k*8 + lane] = es[k];
    }
    __syncthreads();
    if (t < 32){
        float s = 0.f;
        #pragma unroll
        for (int ww = 0; ww < 8; ++ww) s += red[ww][t];
        atomicAdd(&g_sum[b*NCAP + t], s);
    }
}

// ---------------------------------------------------------------------------
// K4: x partial. grid (32 b, 2 dh, 8 jc), 128 thr, pipelined, C de-duplicated.
// (unchanged from round 14 — measured 21.5 us)
// ---------------------------------------------------------------------------
__global__ void __launch_bounds__(128) k_x(const float* __restrict__ u){
    int b = blockIdx.x, dh = blockIdx.y, jc = blockIdx.z;
    int t = threadIdx.x;
    int ig = t & 7, dg = t >> 3;
    __shared__ float Us[32][132];            // [j][128 d]
    __shared__ float Cs[32][37];             // [i][j] scalars, pad 37
    __shared__ float inv[NCAP];
    if (t < 32) inv[t] = 1.0f / g_sum[b*NCAP + t];

    u64 acc[4][4];
    #pragma unroll
    for (int p = 0; p < 4; ++p)
        #pragma unroll
        for (int q = 0; q < 4; ++q) acc[p][q] = 0ull;

    int j0 = jc*128;
    int sj = t >> 5;            // Us: base j
    int sf = t & 31;            // Us: float4 column
    int sci = t >> 5;           //  c: base i
    int scj = t & 31;           //  c: j within tile

    float4 pU[8]; float pB[8];
    #pragma unroll
    for (int p = 0; p < 8; ++p){
        int j = sj + 4*p;
        pU[p] = *(const float4*)(u + ((size_t)b*NN + j0 + j)*DDIM + dh*128 + sf*4);
        int i = sci + 4*p;
        pB[p] = g_b[((size_t)b*NCAP + i)*NN + j0 + scj];
    }

    for (int jt = 0; jt < 128; jt += 32){
        __syncthreads();
        #pragma unroll
        for (int p = 0; p < 8; ++p){
            int j = sj + 4*p;
            *(float4*)&Us[j][sf*4] = pU[p];
            int i = sci + 4*p;
            Cs[i][scj] = __expf(pB[p]) * inv[i];
        }
        __syncthreads();
        if (jt + 32 < 128){
            #pragma unroll
            for (int p = 0; p < 8; ++p){
                int j = sj + 4*p;
                pU[p] = *(const float4*)(u + ((size_t)b*NN + j0 + jt + 32 + j)*DDIM + dh*128 + sf*4);
                int i = sci + 4*p;
                pB[p] = g_b[((size_t)b*NCAP + i)*NN + j0 + jt + 32 + scj];
            }
        }
        #pragma unroll
        for (int jj = 0; jj < 32; ++jj){
            ulonglong2 A0 = *(const ulonglong2*)&Us[jj][dg*8];
            ulonglong2 A1 = *(const ulonglong2*)&Us[jj][dg*8 + 4];
            u64 a[4] = {A0.x, A0.y, A1.x, A1.y};
            u64 c0 = dupf(Cs[ig*4+0][jj]);
            u64 c1 = dupf(Cs[ig*4+1][jj]);
            u64 c2 = dupf(Cs[ig*4+2][jj]);
            u64 c3 = dupf(Cs[ig*4+3][jj]);
            #pragma unroll
            for (int p = 0; p < 4; ++p){
                fma2(acc[p][0], a[p], c0);
                fma2(acc[p][1], a[p], c1);
                fma2(acc[p][2], a[p], c2);
                fma2(acc[p][3], a[p], c3);
            }
        }
    }
    #pragma unroll
    for (int q = 0; q < 4; ++q){
        int i = ig*4 + q;
        float2 r0 = unpk(acc[0][q]), r1 = unpk(acc[1][q]);
        float2 r2 = unpk(acc[2][q]), r3 = unpk(acc[3][q]);
        float* xp = g_xp + (size_t)jc*BB*NCAP*DDIM
                  + ((size_t)b*NCAP + i)*DDIM + dh*128 + dg*8;
        *(float4*)xp       = make_float4(r0.x, r0.y, r1.x, r1.y);
        *(float4*)(xp + 4) = make_float4(r2.x, r2.y, r3.x, r3.y);
    }
}

// ---------------------------------------------------------------------------
extern "C" void kernel_launch(void* const* d_in, const int* in_sizes, int n_in,
                              void* d_out, int out_size){
    const float* u = (const float*)d_in[0];
    const float* W = (const float*)d_in[1];
    if (n_in >= 2 && in_sizes[0] < in_sizes[1]){
        u = (const float*)d_in[1];
        W = (const float*)d_in[0];
    }
    float* out = (float*)d_out;

    const int SV_SMEM  = 256*66*sizeof(float);    // 67584
    const int BUP_SMEM = 256*33*sizeof(float);    // 33792
    static bool attr_done = false;
    if (!attr_done){
        cudaFuncSetAttribute(k_sv<0>,       cudaFuncAttributeMaxDynamicSharedMemorySize, SV_SMEM);
        cudaFuncSetAttribute(k_sv<1>,       cudaFuncAttributeMaxDynamicSharedMemorySize, SV_SMEM);
        cudaFuncSetAttribute(k_sv<2>,       cudaFuncAttributeMaxDynamicSharedMemorySize, SV_SMEM);
        cudaFuncSetAttribute(k_bupd<false>, cudaFuncAttributeMaxDynamicSharedMemorySize, BUP_SMEM);
        cudaFuncSetAttribute(k_bupd<true>,  cudaFuncAttributeMaxDynamicSharedMemorySize, BUP_SMEM);
        attr_done = true;
    }

    // iter 0 (softmax of zeros == mean)
    k_meanpart   <<<dim3(32,8),   256>>>(u);
    k_sv<0>      <<<dim3(32,4),   256, SV_SMEM>>>(W, out);
    k_bupd<false><<<dim3(32,4),   256, BUP_SMEM>>>(u);
    // iter 1
    k_x          <<<dim3(32,2,8), 128>>>(u);
    k_sv<1>      <<<dim3(32,4),   256, SV_SMEM>>>(W, out);
    k_bupd<true> <<<dim3(32,4),   256, BUP_SMEM>>>(u);
    // iter 2 (final)
    k_x          <<<dim3(32,2,8), 128>>>(u);
    k_sv<2>      <<<dim3(32,4),   256, SV_SMEM>>>(W, out);
}